// round 2
// baseline (speedup 1.0000x reference)
#include <cuda_runtime.h>
#include <math.h>

#define L 1024
#define DD 192
#define BSZ 4
#define KK 4
#define NST 16

// ---------------- scratch (no allocs allowed) ----------------
__device__ float  g_xz[BSZ*2*DD*L];     // in_proj output: [0,192)=xx(pre-conv), [192,384)=z raw
__device__ float  g_xs[BSZ*KK*DD*L];    // conv+silu+cross-scan result
__device__ float  g_xdbl[BSZ*KK*38*L];  // x_proj output: rows 0..5 dt_rank, 6..21 B, 22..37 C
__device__ float  g_y[BSZ*KK*DD*L];     // scan output
__device__ float  g_merged[BSZ*DD*L];
__device__ double g_stats[2*BSZ];

__device__ __forceinline__ float siluf(float x){ return x / (1.0f + __expf(-x)); }

// ---------------- generic small SGEMM ----------------
// Y[g] (M x 1024) = W[g % wsel] (M x Kc) * X[g] (Kc x 1024)
__global__ void sgemm_kernel(const float* __restrict__ W, const float* __restrict__ X,
                             float* __restrict__ Y, int M, int Kc,
                             int wPerG, int wsel, int xPerG, int yPerG)
{
    __shared__ float As[8][32];
    __shared__ float Bs[8][128];
    int g = blockIdx.z;
    const float* Wg = W + (g % wsel) * wPerG;
    const float* Xg = X + g * xPerG;
    float*       Yg = Y + g * yPerG;
    int m0 = blockIdx.y * 32;
    int n0 = blockIdx.x * 128;
    int tid = threadIdx.x;
    int tx = tid & 31, ty = tid >> 5;

    float acc[4][4];
#pragma unroll
    for (int i = 0; i < 4; i++)
#pragma unroll
        for (int j = 0; j < 4; j++) acc[i][j] = 0.f;

    int ntiles = Kc >> 3;
    for (int kt = 0; kt < ntiles; kt++) {
        int m = m0 + tx;
        As[ty][tx] = (m < M) ? Wg[m * Kc + kt * 8 + ty] : 0.f;
        const float4* src = (const float4*)(Xg + (kt * 8 + ty) * L + n0);
        ((float4*)&Bs[ty][0])[tx] = src[tx];
        __syncthreads();
#pragma unroll
        for (int q = 0; q < 8; q++) {
            float a0 = As[q][ty*4+0], a1 = As[q][ty*4+1], a2 = As[q][ty*4+2], a3 = As[q][ty*4+3];
            float4 b4 = ((const float4*)&Bs[q][0])[tx];
            acc[0][0] = fmaf(a0,b4.x,acc[0][0]); acc[0][1] = fmaf(a0,b4.y,acc[0][1]);
            acc[0][2] = fmaf(a0,b4.z,acc[0][2]); acc[0][3] = fmaf(a0,b4.w,acc[0][3]);
            acc[1][0] = fmaf(a1,b4.x,acc[1][0]); acc[1][1] = fmaf(a1,b4.y,acc[1][1]);
            acc[1][2] = fmaf(a1,b4.z,acc[1][2]); acc[1][3] = fmaf(a1,b4.w,acc[1][3]);
            acc[2][0] = fmaf(a2,b4.x,acc[2][0]); acc[2][1] = fmaf(a2,b4.y,acc[2][1]);
            acc[2][2] = fmaf(a2,b4.z,acc[2][2]); acc[2][3] = fmaf(a2,b4.w,acc[2][3]);
            acc[3][0] = fmaf(a3,b4.x,acc[3][0]); acc[3][1] = fmaf(a3,b4.y,acc[3][1]);
            acc[3][2] = fmaf(a3,b4.z,acc[3][2]); acc[3][3] = fmaf(a3,b4.w,acc[3][3]);
        }
        __syncthreads();
    }
#pragma unroll
    for (int i = 0; i < 4; i++) {
        int m = m0 + ty * 4 + i;
        if (m < M) {
            float4 v = make_float4(acc[i][0], acc[i][1], acc[i][2], acc[i][3]);
            ((float4*)(Yg + m * L + n0))[tx] = v;
        }
    }
}

// ---------------- fused depthwise conv + silu + cross-scan scatter ----------------
// One thread per (b,d,pixel): conv once, scatter the value to the 4 scan positions.
// Also zeroes the layernorm stats (runs well before merge_kernel in the stream).
__global__ void conv_scan_kernel(const float* __restrict__ cw, const float* __restrict__ cb)
{
    if (blockIdx.x == 0 && threadIdx.x < 2 * BSZ) g_stats[threadIdx.x] = 0.0;
    int t = blockIdx.x * blockDim.x + threadIdx.x;
    if (t >= BSZ * DD * L) return;
    int l = t & (L - 1);
    int d = (t >> 10) % DD;
    int b = (t >> 10) / DD;
    int i = l >> 5, j = l & 31;
    const float* src = g_xz + (b * 2 * DD + d) * L;
    float acc = cb[d];
#pragma unroll
    for (int u = 0; u < 3; u++) {
        int r = i + u - 1;
        if ((unsigned)r < 32u) {
#pragma unroll
            for (int v = 0; v < 3; v++) {
                int c = j + v - 1;
                if ((unsigned)c < 32u)
                    acc = fmaf(cw[d * 9 + u * 3 + v], src[r * 32 + c], acc);
            }
        }
    }
    float val = siluf(acc);
    // scan positions of pixel (i,j) in each of the 4 scan orders (same maps merge uses)
    int l0 = (j << 5)        + (((j & 1) == 0) ? i : 31 - i);
    int l1 = ((31 - j) << 5) + ((j & 1) ? 31 - i : i);
    int l2 = (i << 5)        + (((i & 1) == 0) ? j : 31 - j);
    int l3 = ((31 - i) << 5) + ((i & 1) ? 31 - j : j);
    float* base = g_xs + ((b * 4) * DD + d) * L;
    base[l0]               = val;
    base[DD * L + l1]      = val;
    base[2 * DD * L + l2]  = val;
    base[3 * DD * L + l3]  = val;
}

// ---------------- selective scan with fused delta projection ----------------
// block = 128 threads: 8 d-sequences x 16 states. grid = B*K*(192/8) = 384 blocks.
__global__ void scan_kernel(const float* __restrict__ A_logs, const float* __restrict__ Ds,
                            const float* __restrict__ dt_w, const float* __restrict__ dt_b)
{
    __shared__ float sB[16][65], sC[16][65], sXd[6][65], sDel[8][65], sU[8][65], sY[8][65];
    int blk = blockIdx.x;
    int d0 = (blk % 24) * 8;
    int k  = (blk / 24) & 3;
    int b  = blk / 96;
    int bk = b * 4 + k;
    int tid = threadIdx.x;
    int n  = tid & 15;
    int di = tid >> 4;
    int d  = d0 + di;
    int kd = k * DD + d;

    float Areg = -__expf(A_logs[kd * NST + n]);
    float Dreg = Ds[kd];

    const float* BP  = g_xdbl + (bk * 38 + 6)  * L;
    const float* CP  = g_xdbl + (bk * 38 + 22) * L;
    const float* XdP = g_xdbl + (bk * 38)      * L;
    const float* uP  = g_xs   + (bk * DD + d0) * L;
    float*       yP  = g_y    + (bk * DD + d0) * L;

    float h = 0.f;
    for (int t0 = 0; t0 < L; t0 += 64) {
        for (int idx = tid; idx < 16 * 64; idx += 128) {
            int r = idx >> 6, c = idx & 63;
            sB[r][c] = BP[r * L + t0 + c];
            sC[r][c] = CP[r * L + t0 + c];
        }
        for (int idx = tid; idx < 6 * 64; idx += 128) {
            int r = idx >> 6, c = idx & 63;
            sXd[r][c] = XdP[r * L + t0 + c];
        }
        for (int idx = tid; idx < 8 * 64; idx += 128) {
            int r = idx >> 6, c = idx & 63;
            sU[r][c] = uP[r * L + t0 + c];
        }
        __syncthreads();
        for (int idx = tid; idx < 8 * 64; idx += 128) {
            int r = idx >> 6, c = idx & 63;
            int kdr = k * DD + d0 + r;
            float acc = dt_b[kdr];
#pragma unroll
            for (int q = 0; q < 6; q++)
                acc = fmaf(sXd[q][c], dt_w[kdr * 6 + q], acc);
            sDel[r][c] = (acc > 20.f) ? acc : log1pf(__expf(acc));
        }
        __syncthreads();
#pragma unroll 4
        for (int ll = 0; ll < 64; ll++) {
            float del = sDel[di][ll];
            float u   = sU[di][ll];
            float dA  = __expf(del * Areg);
            h = fmaf(dA, h, del * u * sB[n][ll]);
            float p = h * sC[n][ll];
            p += __shfl_xor_sync(0xffffffffu, p, 1);
            p += __shfl_xor_sync(0xffffffffu, p, 2);
            p += __shfl_xor_sync(0xffffffffu, p, 4);
            p += __shfl_xor_sync(0xffffffffu, p, 8);
            if (n == 0) sY[di][ll] = fmaf(Dreg, u, p);
        }
        __syncthreads();
        for (int idx = tid; idx < 8 * 64; idx += 128) {
            int r = idx >> 6, c = idx & 63;
            yP[r * L + t0 + c] = sY[r][c];
        }
    }
}

// ---------------- cross merge + layernorm stats ----------------
__global__ void merge_kernel()
{
    int b = blockIdx.y;
    int t = blockIdx.x * 256 + threadIdx.x;   // over DD*L
    int l = t & (L - 1);
    int d = t >> 10;
    int i = l >> 5, j = l & 31;
    int l0 = (j << 5)        + (((j & 1) == 0) ? i : 31 - i);
    int l1 = ((31 - j) << 5) + ((j & 1) ? 31 - i : i);
    int l2 = (i << 5)        + (((i & 1) == 0) ? j : 31 - j);
    int l3 = ((31 - i) << 5) + ((i & 1) ? 31 - j : j);
    const float* yb = g_y + ((b * 4) * DD + d) * L;
    float m = yb[l0] + yb[DD * L + l1] + yb[2 * DD * L + l2] + yb[3 * DD * L + l3];
    g_merged[(b * DD + d) * L + l] = m;

    __shared__ float s1[256], s2[256];
    int tx = threadIdx.x;
    s1[tx] = m;
    s2[tx] = m * m;
    __syncthreads();
    for (int s = 128; s > 0; s >>= 1) {
        if (tx < s) { s1[tx] += s1[tx + s]; s2[tx] += s2[tx + s]; }
        __syncthreads();
    }
    if (tx == 0) {
        atomicAdd(&g_stats[2 * b],     (double)s1[0]);
        atomicAdd(&g_stats[2 * b + 1], (double)s2[0]);
    }
}

// ---------------- out_proj GEMM with fused normalize + gate prologue ----------------
// out[g] (96 x 1024) = W (96 x 192) * f(merged, z)[g] (192 x 1024)
__global__ void outproj_kernel(const float* __restrict__ W, float* __restrict__ out,
                               const float* __restrict__ gamma, const float* __restrict__ beta)
{
    __shared__ float As[8][32];
    __shared__ float Bs[8][128];
    int g = blockIdx.z;
    double Ninv = 1.0 / (double)(DD * L);
    double mu_d = g_stats[2 * g] * Ninv;
    double var_d = g_stats[2 * g + 1] * Ninv - mu_d * mu_d;
    float mu  = (float)mu_d;
    float inv = rsqrtf((float)var_d + 1e-6f);

    int m0 = blockIdx.y * 32;
    int n0 = blockIdx.x * 128;
    int tid = threadIdx.x;
    int tx = tid & 31, ty = tid >> 5;

    float acc[4][4];
#pragma unroll
    for (int i = 0; i < 4; i++)
#pragma unroll
        for (int j = 0; j < 4; j++) acc[i][j] = 0.f;

    for (int kt = 0; kt < 24; kt++) {
        int m = m0 + tx;
        As[ty][tx] = W[m * DD + kt * 8 + ty];
        int dd = kt * 8 + ty;
        float ga = gamma[dd] * inv;
        float c0 = beta[dd] - mu * ga;
        const float4* mg = (const float4*)(g_merged + (g * DD + dd) * L + n0);
        const float4* zp = (const float4*)(g_xz + (g * 2 * DD + DD + dd) * L + n0);
        float4 m4 = mg[tx];
        float4 z4 = zp[tx];
        float4 r;
        r.x = fmaf(m4.x, ga, c0) * siluf(z4.x);
        r.y = fmaf(m4.y, ga, c0) * siluf(z4.y);
        r.z = fmaf(m4.z, ga, c0) * siluf(z4.z);
        r.w = fmaf(m4.w, ga, c0) * siluf(z4.w);
        ((float4*)&Bs[ty][0])[tx] = r;
        __syncthreads();
#pragma unroll
        for (int q = 0; q < 8; q++) {
            float a0 = As[q][ty*4+0], a1 = As[q][ty*4+1], a2 = As[q][ty*4+2], a3 = As[q][ty*4+3];
            float4 b4 = ((const float4*)&Bs[q][0])[tx];
            acc[0][0] = fmaf(a0,b4.x,acc[0][0]); acc[0][1] = fmaf(a0,b4.y,acc[0][1]);
            acc[0][2] = fmaf(a0,b4.z,acc[0][2]); acc[0][3] = fmaf(a0,b4.w,acc[0][3]);
            acc[1][0] = fmaf(a1,b4.x,acc[1][0]); acc[1][1] = fmaf(a1,b4.y,acc[1][1]);
            acc[1][2] = fmaf(a1,b4.z,acc[1][2]); acc[1][3] = fmaf(a1,b4.w,acc[1][3]);
            acc[2][0] = fmaf(a2,b4.x,acc[2][0]); acc[2][1] = fmaf(a2,b4.y,acc[2][1]);
            acc[2][2] = fmaf(a2,b4.z,acc[2][2]); acc[2][3] = fmaf(a2,b4.w,acc[2][3]);
            acc[3][0] = fmaf(a3,b4.x,acc[3][0]); acc[3][1] = fmaf(a3,b4.y,acc[3][1]);
            acc[3][2] = fmaf(a3,b4.z,acc[3][2]); acc[3][3] = fmaf(a3,b4.w,acc[3][3]);
        }
        __syncthreads();
    }
#pragma unroll
    for (int i = 0; i < 4; i++) {
        int m = m0 + ty * 4 + i;
        float4 v = make_float4(acc[i][0], acc[i][1], acc[i][2], acc[i][3]);
        ((float4*)(out + (g * 96 + m) * L + n0))[tx] = v;
    }
}

// ---------------- host launch ----------------
extern "C" void kernel_launch(void* const* d_in, const int* in_sizes, int n_in,
                              void* d_out, int out_size)
{
    const float* x        = (const float*)d_in[0];
    const float* in_proj  = (const float*)d_in[1];
    const float* conv_w   = (const float*)d_in[2];
    const float* conv_b   = (const float*)d_in[3];
    const float* x_proj_w = (const float*)d_in[4];
    const float* dt_w     = (const float*)d_in[5];
    const float* dt_b     = (const float*)d_in[6];
    const float* A_logs   = (const float*)d_in[7];
    const float* Ds       = (const float*)d_in[8];
    const float* gamma    = (const float*)d_in[9];
    const float* beta     = (const float*)d_in[10];
    const float* out_proj = (const float*)d_in[11];
    float* out = (float*)d_out;

    void *p_xz, *p_xs, *p_xdbl;
    cudaGetSymbolAddress(&p_xz,   g_xz);
    cudaGetSymbolAddress(&p_xs,   g_xs);
    cudaGetSymbolAddress(&p_xdbl, g_xdbl);

    // 1) in_proj: (384x96) x (96x1024) per batch
    sgemm_kernel<<<dim3(8, 12, 4), 256>>>(in_proj, x, (float*)p_xz,
                                          384, 96, 0, 1, 96 * L, 384 * L);
    // 2) fused depthwise conv + silu + cross-scan scatter (+ stats zeroing)
    conv_scan_kernel<<<(BSZ * DD * L) / 256, 256>>>(conv_w, conv_b);
    // 3) x_proj: (38x192) x (192x1024) per (b,k)
    sgemm_kernel<<<dim3(8, 2, 16), 256>>>(x_proj_w, (const float*)p_xs, (float*)p_xdbl,
                                          38, 192, 38 * 192, 4, 192 * L, 38 * L);
    // 4) selective scan with fused delta projection
    scan_kernel<<<384, 128>>>(A_logs, Ds, dt_w, dt_b);
    // 5) merge + stats
    merge_kernel<<<dim3((DD * L) / 256, BSZ), 256>>>();
    // 6) out_proj with fused normalize/gate -> d_out
    outproj_kernel<<<dim3(8, 3, 4), 256>>>(out_proj, out, gamma, beta);
    (void)in_sizes; (void)n_in; (void)out_size;
}

// round 3
// speedup vs baseline: 1.1707x; 1.1707x over previous
#include <cuda_runtime.h>
#include <math.h>

#define L 1024
#define DD 192
#define BSZ 4
#define KK 4
#define NST 16

// ---------------- scratch (no allocs allowed) ----------------
__device__ float  g_xz[BSZ*2*DD*L];     // in_proj output: [0,192)=xx(pre-conv), [192,384)=z raw
__device__ float  g_xs[BSZ*KK*DD*L];    // conv+silu+cross-scan result
__device__ float  g_xdbl[BSZ*KK*38*L];  // x_proj output: rows 0..5 dt_rank, 6..21 B, 22..37 C
__device__ float  g_y[BSZ*KK*DD*L];     // scan output
__device__ float  g_merged[BSZ*DD*L];
__device__ double g_stats[2*BSZ];

__device__ __forceinline__ float siluf(float x){ return x / (1.0f + __expf(-x)); }

// ---------------- generic small SGEMM ----------------
// Y[g] (M x 1024) = W[g % wsel] (M x Kc) * X[g] (Kc x 1024)
__global__ void sgemm_kernel(const float* __restrict__ W, const float* __restrict__ X,
                             float* __restrict__ Y, int M, int Kc,
                             int wPerG, int wsel, int xPerG, int yPerG)
{
    __shared__ float As[8][32];
    __shared__ float Bs[8][128];
    int g = blockIdx.z;
    const float* Wg = W + (g % wsel) * wPerG;
    const float* Xg = X + g * xPerG;
    float*       Yg = Y + g * yPerG;
    int m0 = blockIdx.y * 32;
    int n0 = blockIdx.x * 128;
    int tid = threadIdx.x;
    int tx = tid & 31, ty = tid >> 5;

    float acc[4][4];
#pragma unroll
    for (int i = 0; i < 4; i++)
#pragma unroll
        for (int j = 0; j < 4; j++) acc[i][j] = 0.f;

    int ntiles = Kc >> 3;
    for (int kt = 0; kt < ntiles; kt++) {
        int m = m0 + tx;
        As[ty][tx] = (m < M) ? Wg[m * Kc + kt * 8 + ty] : 0.f;
        const float4* src = (const float4*)(Xg + (kt * 8 + ty) * L + n0);
        ((float4*)&Bs[ty][0])[tx] = src[tx];
        __syncthreads();
#pragma unroll
        for (int q = 0; q < 8; q++) {
            float a0 = As[q][ty*4+0], a1 = As[q][ty*4+1], a2 = As[q][ty*4+2], a3 = As[q][ty*4+3];
            float4 b4 = ((const float4*)&Bs[q][0])[tx];
            acc[0][0] = fmaf(a0,b4.x,acc[0][0]); acc[0][1] = fmaf(a0,b4.y,acc[0][1]);
            acc[0][2] = fmaf(a0,b4.z,acc[0][2]); acc[0][3] = fmaf(a0,b4.w,acc[0][3]);
            acc[1][0] = fmaf(a1,b4.x,acc[1][0]); acc[1][1] = fmaf(a1,b4.y,acc[1][1]);
            acc[1][2] = fmaf(a1,b4.z,acc[1][2]); acc[1][3] = fmaf(a1,b4.w,acc[1][3]);
            acc[2][0] = fmaf(a2,b4.x,acc[2][0]); acc[2][1] = fmaf(a2,b4.y,acc[2][1]);
            acc[2][2] = fmaf(a2,b4.z,acc[2][2]); acc[2][3] = fmaf(a2,b4.w,acc[2][3]);
            acc[3][0] = fmaf(a3,b4.x,acc[3][0]); acc[3][1] = fmaf(a3,b4.y,acc[3][1]);
            acc[3][2] = fmaf(a3,b4.z,acc[3][2]); acc[3][3] = fmaf(a3,b4.w,acc[3][3]);
        }
        __syncthreads();
    }
#pragma unroll
    for (int i = 0; i < 4; i++) {
        int m = m0 + ty * 4 + i;
        if (m < M) {
            float4 v = make_float4(acc[i][0], acc[i][1], acc[i][2], acc[i][3]);
            ((float4*)(Yg + m * L + n0))[tx] = v;
        }
    }
}

// ---------------- fused depthwise conv + silu + cross-scan scatter ----------------
__global__ void conv_scan_kernel(const float* __restrict__ cw, const float* __restrict__ cb)
{
    if (blockIdx.x == 0 && threadIdx.x < 2 * BSZ) g_stats[threadIdx.x] = 0.0;
    int t = blockIdx.x * blockDim.x + threadIdx.x;
    if (t >= BSZ * DD * L) return;
    int l = t & (L - 1);
    int d = (t >> 10) % DD;
    int b = (t >> 10) / DD;
    int i = l >> 5, j = l & 31;
    const float* src = g_xz + (b * 2 * DD + d) * L;
    float acc = cb[d];
#pragma unroll
    for (int u = 0; u < 3; u++) {
        int r = i + u - 1;
        if ((unsigned)r < 32u) {
#pragma unroll
            for (int v = 0; v < 3; v++) {
                int c = j + v - 1;
                if ((unsigned)c < 32u)
                    acc = fmaf(cw[d * 9 + u * 3 + v], src[r * 32 + c], acc);
            }
        }
    }
    float val = siluf(acc);
    int l0 = (j << 5)        + (((j & 1) == 0) ? i : 31 - i);
    int l1 = ((31 - j) << 5) + ((j & 1) ? 31 - i : i);
    int l2 = (i << 5)        + (((i & 1) == 0) ? j : 31 - j);
    int l3 = ((31 - i) << 5) + ((i & 1) ? 31 - j : j);
    float* base = g_xs + ((b * 4) * DD + d) * L;
    base[l0]               = val;
    base[DD * L + l1]      = val;
    base[2 * DD * L + l2]  = val;
    base[3 * DD * L + l3]  = val;
}

// ---------------- selective scan, smem-transpose reduction (no shfl chain) ----------------
// block = 128 threads = 8 d-sequences x 16 states. grid = 16 bk * 24 dchunks = 384.
__global__ void scan_kernel(const float* __restrict__ A_logs, const float* __restrict__ Ds,
                            const float* __restrict__ dt_w, const float* __restrict__ dt_b)
{
    __shared__ float sB[16][65], sC[16][65], sXd[6][65], sDel[8][65], sU[8][65];
    __shared__ float sP[8][16][17];
    int blk = blockIdx.x;
    int d0 = (blk % 24) * 8;
    int k  = (blk / 24) & 3;
    int b  = blk / 96;
    int bk = b * 4 + k;
    int tid = threadIdx.x;
    int n  = tid & 15;
    int di = tid >> 4;        // 0..7
    int d  = d0 + di;
    int kd = k * DD + d;

    float Areg = -__expf(A_logs[kd * NST + n]);
    float Dreg = Ds[kd];

    // preload delta-projection weights for the rows this thread computes
    int rbase = tid >> 6;     // 0 or 1 ; rows rbase + 2p
    int cdel  = tid & 63;
    float dtw[4][6], dtb[4];
#pragma unroll
    for (int p = 0; p < 4; p++) {
        int kdr = k * DD + d0 + rbase + 2 * p;
        dtb[p] = dt_b[kdr];
#pragma unroll
        for (int q = 0; q < 6; q++) dtw[p][q] = dt_w[kdr * 6 + q];
    }

    const float* BP  = g_xdbl + (bk * 38 + 6)  * L;
    const float* CP  = g_xdbl + (bk * 38 + 22) * L;
    const float* XdP = g_xdbl + (bk * 38)      * L;
    const float* uP  = g_xs   + (bk * DD + d0) * L;
    float*       yP  = g_y    + (bk * DD + d0) * L;

    float h = 0.f;
    for (int t0 = 0; t0 < L; t0 += 64) {
        for (int idx = tid; idx < 16 * 64; idx += 128) {
            int r = idx >> 6, c = idx & 63;
            sB[r][c] = BP[r * L + t0 + c];
            sC[r][c] = CP[r * L + t0 + c];
        }
        for (int idx = tid; idx < 6 * 64; idx += 128) {
            int r = idx >> 6, c = idx & 63;
            sXd[r][c] = XdP[r * L + t0 + c];
        }
        for (int idx = tid; idx < 8 * 64; idx += 128) {
            int r = idx >> 6, c = idx & 63;
            sU[r][c] = uP[r * L + t0 + c];
        }
        __syncthreads();
        // delta projection + softplus
#pragma unroll
        for (int p = 0; p < 4; p++) {
            float acc = dtb[p];
#pragma unroll
            for (int q = 0; q < 6; q++)
                acc = fmaf(sXd[q][cdel], dtw[p][q], acc);
            sDel[rbase + 2 * p][cdel] = (acc > 20.f) ? acc : __logf(1.f + __expf(acc));
        }
        __syncthreads();
        // 4 chunks of 16 timesteps
#pragma unroll
        for (int c16 = 0; c16 < 4; c16++) {
#pragma unroll
            for (int tl = 0; tl < 16; tl++) {
                int ll = c16 * 16 + tl;
                float del = sDel[di][ll];
                float u   = sU[di][ll];
                float dA  = __expf(del * Areg);
                h = fmaf(dA, h, del * u * sB[n][ll]);
                sP[di][n][tl] = h * sC[n][ll];
            }
            __syncwarp();
            float sum = 0.f;
#pragma unroll
            for (int q = 0; q < 16; q++) sum += sP[di][q][n];
            int tt = c16 * 16 + n;
            yP[di * L + t0 + tt] = fmaf(Dreg, sU[di][tt], sum);
            __syncwarp();
        }
        __syncthreads();
    }
}

// ---------------- cross merge + layernorm stats ----------------
__global__ void merge_kernel()
{
    int b = blockIdx.y;
    int t = blockIdx.x * 256 + threadIdx.x;
    int l = t & (L - 1);
    int d = t >> 10;
    int i = l >> 5, j = l & 31;
    int l0 = (j << 5)        + (((j & 1) == 0) ? i : 31 - i);
    int l1 = ((31 - j) << 5) + ((j & 1) ? 31 - i : i);
    int l2 = (i << 5)        + (((i & 1) == 0) ? j : 31 - j);
    int l3 = ((31 - i) << 5) + ((i & 1) ? 31 - j : j);
    const float* yb = g_y + ((b * 4) * DD + d) * L;
    float m = yb[l0] + yb[DD * L + l1] + yb[2 * DD * L + l2] + yb[3 * DD * L + l3];
    g_merged[(b * DD + d) * L + l] = m;

    __shared__ float s1[256], s2[256];
    int tx = threadIdx.x;
    s1[tx] = m;
    s2[tx] = m * m;
    __syncthreads();
    for (int s = 128; s > 0; s >>= 1) {
        if (tx < s) { s1[tx] += s1[tx + s]; s2[tx] += s2[tx + s]; }
        __syncthreads();
    }
    if (tx == 0) {
        atomicAdd(&g_stats[2 * b],     (double)s1[0]);
        atomicAdd(&g_stats[2 * b + 1], (double)s2[0]);
    }
}

// ---------------- out_proj GEMM with fused normalize + gate prologue ----------------
__global__ void outproj_kernel(const float* __restrict__ W, float* __restrict__ out,
                               const float* __restrict__ gamma, const float* __restrict__ beta)
{
    __shared__ float As[8][32];
    __shared__ float Bs[8][128];
    int g = blockIdx.z;
    double Ninv = 1.0 / (double)(DD * L);
    double mu_d = g_stats[2 * g] * Ninv;
    double var_d = g_stats[2 * g + 1] * Ninv - mu_d * mu_d;
    float mu  = (float)mu_d;
    float inv = rsqrtf((float)var_d + 1e-6f);

    int m0 = blockIdx.y * 32;
    int n0 = blockIdx.x * 128;
    int tid = threadIdx.x;
    int tx = tid & 31, ty = tid >> 5;

    float acc[4][4];
#pragma unroll
    for (int i = 0; i < 4; i++)
#pragma unroll
        for (int j = 0; j < 4; j++) acc[i][j] = 0.f;

    for (int kt = 0; kt < 24; kt++) {
        int m = m0 + tx;
        As[ty][tx] = W[m * DD + kt * 8 + ty];
        int dd = kt * 8 + ty;
        float ga = gamma[dd] * inv;
        float c0 = beta[dd] - mu * ga;
        const float4* mg = (const float4*)(g_merged + (g * DD + dd) * L + n0);
        const float4* zp = (const float4*)(g_xz + (g * 2 * DD + DD + dd) * L + n0);
        float4 m4 = mg[tx];
        float4 z4 = zp[tx];
        float4 r;
        r.x = fmaf(m4.x, ga, c0) * siluf(z4.x);
        r.y = fmaf(m4.y, ga, c0) * siluf(z4.y);
        r.z = fmaf(m4.z, ga, c0) * siluf(z4.z);
        r.w = fmaf(m4.w, ga, c0) * siluf(z4.w);
        ((float4*)&Bs[ty][0])[tx] = r;
        __syncthreads();
#pragma unroll
        for (int q = 0; q < 8; q++) {
            float a0 = As[q][ty*4+0], a1 = As[q][ty*4+1], a2 = As[q][ty*4+2], a3 = As[q][ty*4+3];
            float4 b4 = ((const float4*)&Bs[q][0])[tx];
            acc[0][0] = fmaf(a0,b4.x,acc[0][0]); acc[0][1] = fmaf(a0,b4.y,acc[0][1]);
            acc[0][2] = fmaf(a0,b4.z,acc[0][2]); acc[0][3] = fmaf(a0,b4.w,acc[0][3]);
            acc[1][0] = fmaf(a1,b4.x,acc[1][0]); acc[1][1] = fmaf(a1,b4.y,acc[1][1]);
            acc[1][2] = fmaf(a1,b4.z,acc[1][2]); acc[1][3] = fmaf(a1,b4.w,acc[1][3]);
            acc[2][0] = fmaf(a2,b4.x,acc[2][0]); acc[2][1] = fmaf(a2,b4.y,acc[2][1]);
            acc[2][2] = fmaf(a2,b4.z,acc[2][2]); acc[2][3] = fmaf(a2,b4.w,acc[2][3]);
            acc[3][0] = fmaf(a3,b4.x,acc[3][0]); acc[3][1] = fmaf(a3,b4.y,acc[3][1]);
            acc[3][2] = fmaf(a3,b4.z,acc[3][2]); acc[3][3] = fmaf(a3,b4.w,acc[3][3]);
        }
        __syncthreads();
    }
#pragma unroll
    for (int i = 0; i < 4; i++) {
        int m = m0 + ty * 4 + i;
        float4 v = make_float4(acc[i][0], acc[i][1], acc[i][2], acc[i][3]);
        ((float4*)(out + (g * 96 + m) * L + n0))[tx] = v;
    }
}

// ---------------- host launch ----------------
extern "C" void kernel_launch(void* const* d_in, const int* in_sizes, int n_in,
                              void* d_out, int out_size)
{
    const float* x        = (const float*)d_in[0];
    const float* in_proj  = (const float*)d_in[1];
    const float* conv_w   = (const float*)d_in[2];
    const float* conv_b   = (const float*)d_in[3];
    const float* x_proj_w = (const float*)d_in[4];
    const float* dt_w     = (const float*)d_in[5];
    const float* dt_b     = (const float*)d_in[6];
    const float* A_logs   = (const float*)d_in[7];
    const float* Ds       = (const float*)d_in[8];
    const float* gamma    = (const float*)d_in[9];
    const float* beta     = (const float*)d_in[10];
    const float* out_proj = (const float*)d_in[11];
    float* out = (float*)d_out;

    void *p_xz, *p_xs, *p_xdbl;
    cudaGetSymbolAddress(&p_xz,   g_xz);
    cudaGetSymbolAddress(&p_xs,   g_xs);
    cudaGetSymbolAddress(&p_xdbl, g_xdbl);

    sgemm_kernel<<<dim3(8, 12, 4), 256>>>(in_proj, x, (float*)p_xz,
                                          384, 96, 0, 1, 96 * L, 384 * L);
    conv_scan_kernel<<<(BSZ * DD * L) / 256, 256>>>(conv_w, conv_b);
    sgemm_kernel<<<dim3(8, 2, 16), 256>>>(x_proj_w, (const float*)p_xs, (float*)p_xdbl,
                                          38, 192, 38 * 192, 4, 192 * L, 38 * L);
    scan_kernel<<<384, 128>>>(A_logs, Ds, dt_w, dt_b);
    merge_kernel<<<dim3((DD * L) / 256, BSZ), 256>>>();
    outproj_kernel<<<dim3(8, 3, 4), 256>>>(out_proj, out, gamma, beta);
    (void)in_sizes; (void)n_in; (void)out_size;
}